// round 1
// baseline (speedup 1.0000x reference)
#include <cuda_runtime.h>
#include <math.h>

// ---------------------------------------------------------------------------
// FIRE bias: out[h,s,t] = b2[h] + sum_w w2[h,w] * relu(w1[w]*nd(s,t) + b1[w])
// nd(s,t) = log((|s-t|+EPS)*c + 1+EPS) / log(|c*(max(s,thr)+EPS)| + 1+EPS)
//
// Strategy: nd factors into logrel[|s-t|] * invlognorm[s] (1-D tables), and
// the MLP is piecewise-affine in nd over <=W+1 intervals bounded by the sorted
// breakpoints -b1/w1. Precompute per-interval (A[i][h], C[i][h]); main kernel
// does table lookup + 5-step binary search + 12 FMAs per element. Streaming
// 201MB store -> HBM-write bound.
// ---------------------------------------------------------------------------

#define FIRE_EPS 1e-6f
#define FIRE_LOG_BIAS 1.0f
#define MAX_S 4096
#define MAX_W 64
#define MAX_H 16

__device__ float g_logrel[MAX_S];
__device__ float g_invlognorm[MAX_S];
__device__ float g_sortedT[MAX_W];
__device__ float g_A[(MAX_W + 1) * MAX_H];
__device__ float g_C[(MAX_W + 1) * MAX_H];

__global__ void fire_setup(const float* __restrict__ w1, const float* __restrict__ b1,
                           const float* __restrict__ w2, const float* __restrict__ b2,
                           const float* __restrict__ cp, const float* __restrict__ Lm,
                           const float* __restrict__ iL, int S, int W, int H) {
    __shared__ float s_t[MAX_W], s_sl[MAX_W], s_b1[MAX_W];
    __shared__ int s_rank[MAX_W];
    int tid = threadIdx.x;
    float c = cp[0];
    float thr = fabsf(Lm[0] * iL[0]);

    // 1-D tables: log_rel per distance, 1/log_norm per position
    for (int s = tid; s < S; s += blockDim.x) {
        float absrel = (float)s + FIRE_EPS;
        g_logrel[s] = logf(fmaf(absrel, c, FIRE_LOG_BIAS + FIRE_EPS));
        float posn = fmaxf((float)s, thr) + FIRE_EPS;
        g_invlognorm[s] = 1.0f / logf(fabsf(c * posn) + FIRE_LOG_BIAS + FIRE_EPS);
    }

    // breakpoints of the relus (zero-slope units -> +inf, sorted last)
    if (tid < W) {
        float sl = w1[tid];
        float bb = b1[tid];
        s_sl[tid] = sl;
        s_b1[tid] = bb;
        s_t[tid] = (sl != 0.0f) ? (-bb / sl) : __int_as_float(0x7f800000);
    }
    __syncthreads();

    // rank via O(W^2) compare (tie-break by index); scatter into sorted array
    if (tid < W) {
        float tw = s_t[tid];
        int r = 0;
        for (int v = 0; v < W; ++v) {
            float tv = s_t[v];
            if (tv < tw || (tv == tw && v < tid)) r++;
        }
        s_rank[tid] = r;
        g_sortedT[r] = tw;
    }
    __syncthreads();

    // per-(interval, head) affine coefficients
    // interval i = lower_bound count = #{sorted_t < nd}
    //   slope>0 active iff i > rank_w ; slope<0 active iff i <= rank_w ;
    //   slope==0 active iff b1>0 (constant term).
    if (tid < (W + 1) * H) {
        int i = tid / H;
        int h = tid % H;
        float Asum = 0.0f;
        float Csum = b2[h];
        for (int w = 0; w < W; ++w) {
            float sl = s_sl[w];
            bool active;
            if (sl > 0.0f)      active = (i > s_rank[w]);
            else if (sl < 0.0f) active = (i <= s_rank[w]);
            else                active = (s_b1[w] > 0.0f);
            if (active) {
                float ww = w2[h * W + w];
                Asum = fmaf(ww, sl, Asum);
                Csum = fmaf(ww, s_b1[w], Csum);
            }
        }
        g_A[i * H + h] = Asum;
        g_C[i * H + h] = Csum;
    }
}

__global__ void __launch_bounds__(256) fire_main(float* __restrict__ out, int S, int W, int H) {
    __shared__ float shT[MAX_W];
    __shared__ float shA[(MAX_W + 1) * MAX_H];
    __shared__ float shC[(MAX_W + 1) * MAX_H];

    int nAC = (W + 1) * H;
    for (int k = threadIdx.x; k < W; k += blockDim.x) shT[k] = g_sortedT[k];
    for (int k = threadIdx.x; k < nAC; k += blockDim.x) {
        shA[k] = g_A[k];
        shC[k] = g_C[k];
    }
    __syncthreads();

    int s = blockIdx.y;
    int t0 = (blockIdx.x * blockDim.x + threadIdx.x) * 4;
    if (t0 >= S) return;

    float invln = __ldg(&g_invlognorm[s]);

    float nd[4];
    int row[4];
#pragma unroll
    for (int e = 0; e < 4; ++e) {
        int t = t0 + e;
        if (t >= S) t = S - 1;  // clamped duplicates; tail handled below
        int d = (s >= t) ? (s - t) : (t - s);
        float v = __ldg(&g_logrel[d]) * invln;
        nd[e] = v;
        // lower_bound over sorted breakpoints (inf-padded): i = #{shT[k] < v}
        int lo = 0, hi = W;
        while (lo < hi) {
            int mid = (lo + hi) >> 1;
            if (shT[mid] < v) lo = mid + 1;
            else hi = mid;
        }
        row[e] = lo * H;
    }

    size_t plane = (size_t)S * (size_t)S;
    size_t base = (size_t)s * (size_t)S + (size_t)t0;

    if (t0 + 3 < S) {
#pragma unroll
        for (int h = 0; h < MAX_H; ++h) {
            if (h >= H) break;
            float4 v;
            v.x = fmaf(shA[row[0] + h], nd[0], shC[row[0] + h]);
            v.y = fmaf(shA[row[1] + h], nd[1], shC[row[1] + h]);
            v.z = fmaf(shA[row[2] + h], nd[2], shC[row[2] + h]);
            v.w = fmaf(shA[row[3] + h], nd[3], shC[row[3] + h]);
            *reinterpret_cast<float4*>(out + (size_t)h * plane + base) = v;
        }
    } else {
        // scalar tail (unused when S % 4 == 0)
        for (int e = 0; e < 4; ++e) {
            int t = t0 + e;
            if (t >= S) break;
            for (int h = 0; h < H; ++h)
                out[(size_t)h * plane + (size_t)s * S + t] =
                    fmaf(shA[row[e] + h], nd[e], shC[row[e] + h]);
        }
    }
}

extern "C" void kernel_launch(void* const* d_in, const int* in_sizes, int n_in,
                              void* d_out, int out_size) {
    // inputs: x, w1, b1, w2, b2, c, L_multiplier, init_L  (x unused by the math)
    const float* w1 = (const float*)d_in[1];
    const float* b1 = (const float*)d_in[2];
    const float* w2 = (const float*)d_in[3];
    const float* b2 = (const float*)d_in[4];
    const float* c  = (const float*)d_in[5];
    const float* Lm = (const float*)d_in[6];
    const float* iL = (const float*)d_in[7];

    int W = in_sizes[1];          // w1 is (W,1)
    int H = in_sizes[4];          // b2 is (H,)
    long long ss = (long long)out_size / (long long)H;  // S*S
    int S = (int)(sqrt((double)ss) + 0.5);

    fire_setup<<<1, 1024>>>(w1, b1, w2, b2, c, Lm, iL, S, W, H);

    dim3 block(256);
    dim3 grid((unsigned)((S + 1023) / 1024), (unsigned)S);
    fire_main<<<grid, block>>>((float*)d_out, S, W, H);
}

// round 3
// speedup vs baseline: 1.0107x; 1.0107x over previous
#include <cuda_runtime.h>
#include <math.h>

// ---------------------------------------------------------------------------
// FIRE bias: out[h,s,t] = b2[h] + sum_w w2[h,w] * relu(w1[w]*nd(s,t) + b1[w])
// nd(s,t) = logrel[|s-t|] * invlognorm[s]  (two 1-D tables)
// MLP is piecewise-affine in nd: bias_h = A[i][h]*nd + C[i][h] over <=W+1
// intervals (sorted breakpoints -b1/w1). Main kernel: table lookup, interval
// search (shared across 4 elems in the common case), 12 FMAs/elem, float4
// streaming stores. Pure HBM-write-bound.
// ---------------------------------------------------------------------------

#define FIRE_EPS 1e-6f
#define FIRE_LOG_BIAS 1.0f
#define MAX_S 4096
#define MAX_W 64
#define MAX_H 16

__device__ float g_logrel[MAX_S];
__device__ float g_invlognorm[MAX_S];
__device__ float g_sortedT[MAX_W];
__device__ float g_A[(MAX_W + 1) * MAX_H];
__device__ float g_C[(MAX_W + 1) * MAX_H];

// ---- setup part 1: 1-D tables, parallel across blocks --------------------
__global__ void fire_tables(const float* __restrict__ cp, const float* __restrict__ Lm,
                            const float* __restrict__ iL, int S) {
    float c = cp[0];
    float thr = fabsf(Lm[0] * iL[0]);
    int i0 = blockIdx.x * blockDim.x + threadIdx.x;
    int stride = gridDim.x * blockDim.x;
    for (int s = i0; s < S; s += stride) {
        float absrel = (float)s + FIRE_EPS;
        g_logrel[s] = logf(fmaf(absrel, c, FIRE_LOG_BIAS + FIRE_EPS));
        float posn = fmaxf((float)s, thr) + FIRE_EPS;
        g_invlognorm[s] = 1.0f / logf(fabsf(c * posn) + FIRE_LOG_BIAS + FIRE_EPS);
    }
}

// ---- setup part 2: breakpoints + per-interval affine coeffs (1 block) ----
__global__ void fire_coeffs(const float* __restrict__ w1, const float* __restrict__ b1,
                            const float* __restrict__ w2, const float* __restrict__ b2,
                            int W, int H) {
    __shared__ float s_t[MAX_W], s_sl[MAX_W], s_b1[MAX_W];
    __shared__ int s_rank[MAX_W];
    int tid = threadIdx.x;

    if (tid < W) {
        float sl = w1[tid];
        float bb = b1[tid];
        s_sl[tid] = sl;
        s_b1[tid] = bb;
        s_t[tid] = (sl != 0.0f) ? (-bb / sl) : __int_as_float(0x7f800000);
    }
    __syncthreads();
    if (tid < W) {
        float tw = s_t[tid];
        int r = 0;
        for (int v = 0; v < W; ++v) {
            float tv = s_t[v];
            if (tv < tw || (tv == tw && v < tid)) r++;
        }
        s_rank[tid] = r;
        g_sortedT[r] = tw;
    }
    __syncthreads();
    // interval i = #{sorted breakpoints < nd}
    for (int k = tid; k < (W + 1) * H; k += blockDim.x) {
        int i = k / H;
        int h = k % H;
        float Asum = 0.0f;
        float Csum = b2[h];
        for (int w = 0; w < W; ++w) {
            float sl = s_sl[w];
            bool active;
            if (sl > 0.0f)      active = (i > s_rank[w]);
            else if (sl < 0.0f) active = (i <= s_rank[w]);
            else                active = (s_b1[w] > 0.0f);
            if (active) {
                float ww = w2[h * W + w];
                Asum = fmaf(ww, sl, Asum);
                Csum = fmaf(ww, s_b1[w], Csum);
            }
        }
        g_A[i * H + h] = Asum;
        g_C[i * H + h] = Csum;
    }
}

// ---- main kernel ---------------------------------------------------------
template <int H, int W>
__global__ void __launch_bounds__(256) fire_main_t(float* __restrict__ out, int S) {
    __shared__ float shT[W];
    __shared__ float shA[(W + 1) * H];
    __shared__ float shC[(W + 1) * H];

    for (int k = threadIdx.x; k < W; k += blockDim.x) shT[k] = g_sortedT[k];
    for (int k = threadIdx.x; k < (W + 1) * H; k += blockDim.x) {
        shA[k] = g_A[k];
        shC[k] = g_C[k];
    }
    __syncthreads();

    int s = blockIdx.y;
    int t0 = (blockIdx.x * blockDim.x + threadIdx.x) * 4;
    if (t0 + 3 >= S) {
        if (t0 >= S) return;
        // scalar tail (unused when S % 4 == 0)
        float invln = __ldg(&g_invlognorm[s]);
        for (int t = t0; t < S; ++t) {
            int d = (s >= t) ? (s - t) : (t - s);
            float v = __ldg(&g_logrel[d]) * invln;
            int lo = 0, hi = W;
            while (lo < hi) { int m = (lo + hi) >> 1; if (shT[m] < v) lo = m + 1; else hi = m; }
            for (int h = 0; h < H; ++h)
                out[(size_t)h * S * S + (size_t)s * S + t] = fmaf(shA[lo * H + h], v, shC[lo * H + h]);
        }
        return;
    }

    float invln = __ldg(&g_invlognorm[s]);

    float nd[4];
#pragma unroll
    for (int e = 0; e < 4; ++e) {
        int t = t0 + e;
        int d = (s >= t) ? (s - t) : (t - s);
        nd[e] = __ldg(&g_logrel[d]) * invln;
    }
    float ndmin = fminf(fminf(nd[0], nd[1]), fminf(nd[2], nd[3]));
    float ndmax = fmaxf(fmaxf(nd[0], nd[1]), fmaxf(nd[2], nd[3]));

    // lower_bound: i = #{shT[k] < v}
    int lo = 0, hi = W;
    while (lo < hi) { int m = (lo + hi) >> 1; if (shT[m] < ndmin) lo = m + 1; else hi = m; }
    int imin = lo;
    lo = imin; hi = W;
    while (lo < hi) { int m = (lo + hi) >> 1; if (shT[m] < ndmax) lo = m + 1; else hi = m; }
    int imax = lo;

    size_t plane = (size_t)S * (size_t)S;
    size_t base = (size_t)s * (size_t)S + (size_t)t0;

    if (imin == imax) {
        // common case: all 4 elements in the same affine interval — hoist
        // the H (A, C) pairs into registers, one LDS pair per head.
        int r = imin * H;
#pragma unroll
        for (int h = 0; h < H; ++h) {
            float a = shA[r + h];
            float cc = shC[r + h];
            float4 v;
            v.x = fmaf(a, nd[0], cc);
            v.y = fmaf(a, nd[1], cc);
            v.z = fmaf(a, nd[2], cc);
            v.w = fmaf(a, nd[3], cc);
            __stcs(reinterpret_cast<float4*>(out + (size_t)h * plane + base), v);
        }
    } else {
        int row[4];
#pragma unroll
        for (int e = 0; e < 4; ++e) {
            float v = nd[e];
            int l = imin, hh = imax;
            while (l < hh) { int m = (l + hh) >> 1; if (shT[m] < v) l = m + 1; else hh = m; }
            row[e] = l * H;
        }
#pragma unroll
        for (int h = 0; h < H; ++h) {
            float4 v;
            v.x = fmaf(shA[row[0] + h], nd[0], shC[row[0] + h]);
            v.y = fmaf(shA[row[1] + h], nd[1], shC[row[1] + h]);
            v.z = fmaf(shA[row[2] + h], nd[2], shC[row[2] + h]);
            v.w = fmaf(shA[row[3] + h], nd[3], shC[row[3] + h]);
            __stcs(reinterpret_cast<float4*>(out + (size_t)h * plane + base), v);
        }
    }
}

// generic fallback (runtime H, W)
__global__ void __launch_bounds__(256) fire_main_g(float* __restrict__ out, int S, int W, int H) {
    __shared__ float shT[MAX_W];
    __shared__ float shA[(MAX_W + 1) * MAX_H];
    __shared__ float shC[(MAX_W + 1) * MAX_H];
    for (int k = threadIdx.x; k < W; k += blockDim.x) shT[k] = g_sortedT[k];
    for (int k = threadIdx.x; k < (W + 1) * H; k += blockDim.x) {
        shA[k] = g_A[k];
        shC[k] = g_C[k];
    }
    __syncthreads();
    int s = blockIdx.y;
    int t0 = (blockIdx.x * blockDim.x + threadIdx.x) * 4;
    if (t0 >= S) return;
    float invln = __ldg(&g_invlognorm[s]);
    for (int e = 0; e < 4; ++e) {
        int t = t0 + e;
        if (t >= S) break;
        int d = (s >= t) ? (s - t) : (t - s);
        float v = __ldg(&g_logrel[d]) * invln;
        int lo = 0, hi = W;
        while (lo < hi) { int m = (lo + hi) >> 1; if (shT[m] < v) lo = m + 1; else hi = m; }
        for (int h = 0; h < H; ++h)
            out[(size_t)h * S * S + (size_t)s * S + t] = fmaf(shA[lo * H + h], v, shC[lo * H + h]);
    }
}

extern "C" void kernel_launch(void* const* d_in, const int* in_sizes, int n_in,
                              void* d_out, int out_size) {
    // inputs: x, w1, b1, w2, b2, c, L_multiplier, init_L  (x unused by the math)
    const float* w1 = (const float*)d_in[1];
    const float* b1 = (const float*)d_in[2];
    const float* w2 = (const float*)d_in[3];
    const float* b2 = (const float*)d_in[4];
    const float* c  = (const float*)d_in[5];
    const float* Lm = (const float*)d_in[6];
    const float* iL = (const float*)d_in[7];

    int W = in_sizes[1];          // w1 is (W,1)
    int H = in_sizes[4];          // b2 is (H,)
    long long ss = (long long)out_size / (long long)H;  // S*S
    int S = (int)(sqrt((double)ss) + 0.5);

    fire_tables<<<8, 256>>>(c, Lm, iL, S);
    fire_coeffs<<<1, 512>>>(w1, b1, w2, b2, W, H);

    dim3 block(256);
    dim3 grid((unsigned)((S + 1023) / 1024), (unsigned)S);
    if (H == 12 && W == 32) {
        fire_main_t<12, 32><<<grid, block>>>((float*)d_out, S);
    } else {
        fire_main_g<<<grid, block>>>((float*)d_out, S, W, H);
    }
}